// round 10
// baseline (speedup 1.0000x reference)
#include <cuda_runtime.h>
#include <math_constants.h>
#include <cstdint>

#define BATCH 16
#define SEQ   4096
#define NT    1024
#define NEG   (-CUDART_INF_F)

__global__ __launch_bounds__(NT, 1)
void pred_head_row(const float4* __restrict__ s4,
                   const float4* __restrict__ e4,
                   float* __restrict__ out) {
    // Log-space segmented scans, segment = 32 elements (8 lanes x 4 elems).
    // pfxE[i]  = max end-logit[seg_start(i)..i]        (+32 back pad of -INF)
    // sfxS[32+i] = max start-logit[i..seg_end(i)]      (front 32 pad of -INF)
    __shared__ float pfxE[SEQ + 32];
    __shared__ float sfxS[SEQ + 32];
    __shared__ float redS[32], redE[32];
    __shared__ float wav[32], wav2[32];
    __shared__ int   wai[32], wai2[32];

    const int t    = threadIdx.x;
    const int lane = t & 31;
    const int wid  = t >> 5;
    const int row  = blockIdx.x;
    const int base = t * 4;
    const int oct  = lane & 7;

    // ---- pads ----
    if (t < 32) { pfxE[SEQ + t] = NEG; sfxS[t] = NEG; }

    // ---- load (LDG.128) ----
    float4 sv4 = s4[row * (SEQ / 4) + t];
    float4 ev4 = e4[row * (SEQ / 4) + t];
    float sl[4] = {sv4.x, sv4.y, sv4.z, sv4.w};
    float el[4] = {ev4.x, ev4.y, ev4.z, ev4.w};

    // ---- thread-local prefix/suffix ----
    float lpS[4], lsS[4], lpE[4], lsE[4];
    lpS[0] = sl[0]; lpE[0] = el[0];
    #pragma unroll
    for (int k = 1; k < 4; k++) { lpS[k] = fmaxf(lpS[k-1], sl[k]); lpE[k] = fmaxf(lpE[k-1], el[k]); }
    lsS[3] = sl[3]; lsE[3] = el[3];
    #pragma unroll
    for (int k = 2; k >= 0; k--) { lsS[k] = fmaxf(lsS[k+1], sl[k]); lsE[k] = fmaxf(lsE[k+1], el[k]); }

    // ---- octet (8-lane) scans on thread aggregates ----
    const float aggS = lpS[3], aggE = lpE[3];
    float ipS = aggS, ipE = aggE, isS = aggS, isE = aggE;   // inclusive pfx/sfx within octet
    #pragma unroll
    for (int o = 1; o < 8; o <<= 1) {
        float a = __shfl_up_sync(0xffffffffu, ipS, o);   if (oct >= o)     ipS = fmaxf(ipS, a);
        float b = __shfl_up_sync(0xffffffffu, ipE, o);   if (oct >= o)     ipE = fmaxf(ipE, b);
        float c = __shfl_down_sync(0xffffffffu, isS, o); if (oct + o < 8)  isS = fmaxf(isS, c);
        float d = __shfl_down_sync(0xffffffffu, isE, o); if (oct + o < 8)  isE = fmaxf(isE, d);
    }
    // exclusive versions (preceding / following lanes only)
    float epS = __shfl_up_sync(0xffffffffu, ipS, 1);   epS = (oct >= 1) ? epS : NEG;
    float epE = __shfl_up_sync(0xffffffffu, ipE, 1);   epE = (oct >= 1) ? epE : NEG;
    float esS = __shfl_down_sync(0xffffffffu, isS, 1); esS = (oct < 7) ? esS : NEG;
    float esE = __shfl_down_sync(0xffffffffu, isE, 1); esE = (oct < 7) ? esE : NEG;

    // ---- elementwise within-segment scans ----
    float PS[4], SE[4];          // PS: own prefix of start (backward); SE: own suffix of end (forward)
    float4 stP, stS;             // pfxE (end prefix) and sfxS (start suffix) for smem
    #pragma unroll
    for (int k = 0; k < 4; k++) {
        PS[k] = fmaxf(epS, lpS[k]);
        SE[k] = fmaxf(esE, lsE[k]);
        ((float*)&stP)[k] = fmaxf(epE, lpE[k]);   // end-logit prefix
        ((float*)&stS)[k] = fmaxf(esS, lsS[k]);   // start-logit suffix
    }
    *(float4*)&pfxE[base]      = stP;
    *(float4*)&sfxS[32 + base] = stS;

    // ---- exps (MUFU; off the argmax chain) + per-warp dual sums ----
    float exS[4], exE[4];
    #pragma unroll
    for (int k = 0; k < 4; k++) { exS[k] = __expf(sl[k]); exE[k] = __expf(el[k]); }
    float a = (exS[0] + exS[1]) + (exS[2] + exS[3]);
    float c = (exE[0] + exE[1]) + (exE[2] + exE[3]);
    #pragma unroll
    for (int o = 16; o; o >>= 1) {
        a += __shfl_xor_sync(0xffffffffu, a, o);
        c += __shfl_xor_sync(0xffffffffu, c, o);
    }
    if (lane == 0) { redS[wid] = a; redE[wid] = c; }

    __syncthreads();   // bar1: scan arrays + sum partials visible

    // ---- width-31 windows + log-space scores + per-thread argmax ----
    float bsv = NEG, bev = NEG; int bsi = 0, bei = 0;
    #pragma unroll
    for (int k = 0; k < 4; k++) {
        const int i = base + k;
        const int p = i & 31;
        // F[i] = max end[i..min(i+30,SEQ-1)]
        float Fb = pfxE[i + 30];
        float F  = (p == 0) ? Fb : (p == 1) ? SE[k] : fmaxf(SE[k], Fb);
        // B[j] = max start[max(j-30,0)..j];  sfxS index (j-30)+32 = i+2
        float Bb = sfxS[i + 2];
        float B  = (p == 30) ? PS[k] : (p == 31) ? Bb : fmaxf(PS[k], Bb);
        float s1 = sl[k] + F;
        if (s1 > bsv) { bsv = s1; bsi = i; }
        float s2 = el[k] + B;
        if (s2 > bev) { bev = s2; bei = i; }
    }
    // warp dual argmax (first-index tie-break)
    #pragma unroll
    for (int o = 16; o; o >>= 1) {
        float ov = __shfl_xor_sync(0xffffffffu, bsv, o);
        int   oi = __shfl_xor_sync(0xffffffffu, bsi, o);
        if (ov > bsv || (ov == bsv && oi < bsi)) { bsv = ov; bsi = oi; }
        float ov2 = __shfl_xor_sync(0xffffffffu, bev, o);
        int   oi2 = __shfl_xor_sync(0xffffffffu, bei, o);
        if (ov2 > bev || (ov2 == bev && oi2 < bei)) { bev = ov2; bei = oi2; }
    }
    if (lane == 0) { wav[wid] = bsv; wai[wid] = bsi; wav2[wid] = bev; wai2[wid] = bei; }

    // ---- every warp redundantly folds global sums (partials ready since bar1) ----
    {
        float v1 = redS[lane], v2 = redE[lane];
        #pragma unroll
        for (int o = 16; o; o >>= 1) {
            v1 += __shfl_xor_sync(0xffffffffu, v1, o);
            v2 += __shfl_xor_sync(0xffffffffu, v2, o);
        }
        const float invS = __frcp_rn(v1);
        const float invE = __frcp_rn(v2);
        float4 po, qo;
        po.x = exS[0] * invS; po.y = exS[1] * invS; po.z = exS[2] * invS; po.w = exS[3] * invS;
        qo.x = exE[0] * invE; qo.y = exE[1] * invE; qo.z = exE[2] * invE; qo.w = exE[3] * invE;
        ((float4*)(out + row * SEQ))[t]               = po;
        ((float4*)(out + BATCH * SEQ + row * SEQ))[t] = qo;
    }

    __syncthreads();   // bar2: warp argmax partials visible

    // ---- final 32-way argmax: warp 0 = start, warp 1 = end ----
    if (wid == 0) {
        float v = wav[lane]; int i = wai[lane];
        #pragma unroll
        for (int o = 16; o; o >>= 1) {
            float ov = __shfl_xor_sync(0xffffffffu, v, o);
            int   oi = __shfl_xor_sync(0xffffffffu, i, o);
            if (ov > v || (ov == v && oi < i)) { v = ov; i = oi; }
        }
        if (lane == 0) out[2 * BATCH * SEQ + row] = (float)i;
    } else if (wid == 1) {
        float v = wav2[lane]; int i = wai2[lane];
        #pragma unroll
        for (int o = 16; o; o >>= 1) {
            float ov = __shfl_xor_sync(0xffffffffu, v, o);
            int   oi = __shfl_xor_sync(0xffffffffu, i, o);
            if (ov > v || (ov == v && oi < i)) { v = ov; i = oi; }
        }
        if (lane == 0) out[2 * BATCH * SEQ + BATCH + row] = (float)i;
    }
}

extern "C" void kernel_launch(void* const* d_in, const int* in_sizes, int n_in,
                              void* d_out, int out_size) {
    const float4* s4 = (const float4*)d_in[0];
    const float4* e4 = (const float4*)d_in[1];
    float* out = (float*)d_out;
    pred_head_row<<<BATCH, NT>>>(s4, e4, out);
}

// round 12
// speedup vs baseline: 1.0037x; 1.0037x over previous
#include <cuda_runtime.h>
#include <math_constants.h>
#include <cstdint>

#define BATCH 16
#define SEQ   4096
#define NTC   512
#define EPT   8            // elements per thread (full row / 512 threads)
#define NEG   (-CUDART_INF_F)

__global__ __launch_bounds__(NTC, 1)
void pred_head_zc(const float4* __restrict__ s4,
                  const float4* __restrict__ e4,
                  float* __restrict__ out) {
    // Segment = 32 elements = 4 threads (quad). Log-space scans on raw logits.
    // pfxE[i]:    max end-logit[seg_start(i)..i]   (+32 tail pad of NEG)
    // sfxS[32+i]: max start-logit[i..seg_end(i)]   (32 head pad of NEG)
    __shared__ float pfxE[SEQ + 32];
    __shared__ float sfxS[SEQ + 32];
    __shared__ float redS[16], redE[16];
    __shared__ float wav[16], wav2[16];
    __shared__ int   wai[16], wai2[16];

    const int t     = threadIdx.x;
    const int lane  = t & 31;
    const int wid   = t >> 5;
    const int row   = blockIdx.x >> 3;
    const int slice = blockIdx.x & 7;
    const int base  = t * EPT;
    const int q     = lane & 3;           // position within quad (segment)

    if (t < 32) { pfxE[SEQ + t] = NEG; sfxS[t] = NEG; }

    // ---- full-row load: 2 float4 per tensor per thread ----
    const float4* srow4 = s4 + row * (SEQ / 4);
    const float4* erow4 = e4 + row * (SEQ / 4);
    float4 sA = srow4[t * 2], sB = srow4[t * 2 + 1];
    float4 eA = erow4[t * 2], eB = erow4[t * 2 + 1];
    float sl[EPT] = {sA.x, sA.y, sA.z, sA.w, sB.x, sB.y, sB.z, sB.w};
    float el[EPT] = {eA.x, eA.y, eA.z, eA.w, eB.x, eB.y, eB.z, eB.w};

    // ---- thread-local prefix/suffix maxima ----
    float lpS[EPT], lsS[EPT], lpE[EPT], lsE[EPT];
    lpS[0] = sl[0]; lpE[0] = el[0];
    #pragma unroll
    for (int k = 1; k < EPT; k++) { lpS[k] = fmaxf(lpS[k-1], sl[k]); lpE[k] = fmaxf(lpE[k-1], el[k]); }
    lsS[EPT-1] = sl[EPT-1]; lsE[EPT-1] = el[EPT-1];
    #pragma unroll
    for (int k = EPT-2; k >= 0; k--) { lsS[k] = fmaxf(lsS[k+1], sl[k]); lsE[k] = fmaxf(lsE[k+1], el[k]); }

    // ---- quad (4-lane) scans on thread aggregates ----
    float ipS = lpS[EPT-1], ipE = lpE[EPT-1];   // inclusive prefix within quad
    float isS = lpS[EPT-1], isE = lpE[EPT-1];   // inclusive suffix within quad
    #pragma unroll
    for (int o = 1; o < 4; o <<= 1) {
        float a = __shfl_up_sync(0xffffffffu, ipS, o);   if (q >= o)    ipS = fmaxf(ipS, a);
        float b = __shfl_up_sync(0xffffffffu, ipE, o);   if (q >= o)    ipE = fmaxf(ipE, b);
        float c = __shfl_down_sync(0xffffffffu, isS, o); if (q + o < 4) isS = fmaxf(isS, c);
        float d = __shfl_down_sync(0xffffffffu, isE, o); if (q + o < 4) isE = fmaxf(isE, d);
    }
    float epS = __shfl_up_sync(0xffffffffu, ipS, 1);   epS = (q >= 1) ? epS : NEG;
    float epE = __shfl_up_sync(0xffffffffu, ipE, 1);   epE = (q >= 1) ? epE : NEG;
    float esS = __shfl_down_sync(0xffffffffu, isS, 1); esS = (q < 3) ? esS : NEG;
    float esE = __shfl_down_sync(0xffffffffu, isE, 1); esE = (q < 3) ? esE : NEG;

    // ---- within-segment scan arrays -> smem (2 STS.128 each) ----
    float4 p0, p1, s0, s1;
    #pragma unroll
    for (int k = 0; k < 4; k++) {
        ((float*)&p0)[k] = fmaxf(epE, lpE[k]);
        ((float*)&p1)[k] = fmaxf(epE, lpE[k + 4]);
        ((float*)&s0)[k] = fmaxf(esS, lsS[k]);
        ((float*)&s1)[k] = fmaxf(esS, lsS[k + 4]);
    }
    *(float4*)&pfxE[base]          = p0;
    *(float4*)&pfxE[base + 4]      = p1;
    *(float4*)&sfxS[32 + base]     = s0;
    *(float4*)&sfxS[32 + base + 4] = s1;

    // ---- exps (MUFU, off the argmax chain) + per-warp dual sums ----
    float exS[EPT], exE[EPT];
    float a = 0.f, c = 0.f;
    #pragma unroll
    for (int k = 0; k < EPT; k++) {
        exS[k] = __expf(sl[k]); exE[k] = __expf(el[k]);
        a += exS[k]; c += exE[k];
    }
    #pragma unroll
    for (int o = 16; o; o >>= 1) {
        a += __shfl_xor_sync(0xffffffffu, a, o);
        c += __shfl_xor_sync(0xffffffffu, c, o);
    }
    if (lane == 0) { redS[wid] = a; redE[wid] = c; }

    __syncthreads();   // bar1: scan arrays + sum partials visible

    // ---- width-31 windows + log-space scores + per-thread argmax ----
    float bsv = NEG, bev = NEG; int bsi = 0, bei = 0;
    #pragma unroll
    for (int k = 0; k < EPT; k++) {
        const int i = base + k;
        const int p = i & 31;
        const float SE = fmaxf(esE, lsE[k]);   // end suffix   [i..seg_end]
        const float PS = fmaxf(epS, lpS[k]);   // start prefix [seg_start..i]
        float Fb = pfxE[i + 30];
        float F  = (p == 0) ? Fb : (p == 1) ? SE : fmaxf(SE, Fb);
        float Bb = sfxS[i + 2];
        float B  = (p == 30) ? PS : (p == 31) ? Bb : fmaxf(PS, Bb);
        float v1 = sl[k] + F;
        if (v1 > bsv) { bsv = v1; bsi = i; }
        float v2 = el[k] + B;
        if (v2 > bev) { bev = v2; bei = i; }
    }
    #pragma unroll
    for (int o = 16; o; o >>= 1) {
        float ov = __shfl_xor_sync(0xffffffffu, bsv, o);
        int   oi = __shfl_xor_sync(0xffffffffu, bsi, o);
        if (ov > bsv || (ov == bsv && oi < bsi)) { bsv = ov; bsi = oi; }
        float ov2 = __shfl_xor_sync(0xffffffffu, bev, o);
        int   oi2 = __shfl_xor_sync(0xffffffffu, bei, o);
        if (ov2 > bev || (ov2 == bev && oi2 < bei)) { bev = ov2; bei = oi2; }
    }
    if (lane == 0) { wav[wid] = bsv; wai[wid] = bsi; wav2[wid] = bev; wai2[wid] = bei; }

    // ---- fold global sums (every warp, redundant) + slice prob writes ----
    {
        float v1 = (lane < 16) ? redS[lane] : 0.f;
        float v2 = (lane < 16) ? redE[lane] : 0.f;
        #pragma unroll
        for (int o = 8; o; o >>= 1) {
            v1 += __shfl_xor_sync(0xffffffffu, v1, o);
            v2 += __shfl_xor_sync(0xffffffffu, v2, o);
        }
        const float invS = __frcp_rn(__shfl_sync(0xffffffffu, v1, 0));
        const float invE = __frcp_rn(__shfl_sync(0xffffffffu, v2, 0));
        if ((t >> 6) == slice) {   // this thread's 8 elems lie in our slice
            float4 oS0, oS1, oE0, oE1;
            #pragma unroll
            for (int k = 0; k < 4; k++) {
                ((float*)&oS0)[k] = exS[k]     * invS;
                ((float*)&oS1)[k] = exS[k + 4] * invS;
                ((float*)&oE0)[k] = exE[k]     * invE;
                ((float*)&oE1)[k] = exE[k + 4] * invE;
            }
            float4* os = (float4*)(out + row * SEQ);
            float4* oe = (float4*)(out + BATCH * SEQ + row * SEQ);
            os[t * 2]     = oS0;
            os[t * 2 + 1] = oS1;
            oe[t * 2]     = oE0;
            oe[t * 2 + 1] = oE1;
        }
    }

    __syncthreads();   // bar2: warp argmax partials visible

    // ---- final dual argmax (warp0 = start, warp1 = end); slice 0 writes ----
    if (slice == 0) {
        if (wid == 0) {
            float v = (lane < 16) ? wav[lane] : NEG;
            int   i = (lane < 16) ? wai[lane] : 0x7fffffff;
            #pragma unroll
            for (int o = 8; o; o >>= 1) {
                float ov = __shfl_xor_sync(0xffffffffu, v, o);
                int   oi = __shfl_xor_sync(0xffffffffu, i, o);
                if (ov > v || (ov == v && oi < i)) { v = ov; i = oi; }
            }
            if (lane == 0) out[2 * BATCH * SEQ + row] = (float)i;
        } else if (wid == 1) {
            float v = (lane < 16) ? wav2[lane] : NEG;
            int   i = (lane < 16) ? wai2[lane] : 0x7fffffff;
            #pragma unroll
            for (int o = 8; o; o >>= 1) {
                float ov = __shfl_xor_sync(0xffffffffu, v, o);
                int   oi = __shfl_xor_sync(0xffffffffu, i, o);
                if (ov > v || (ov == v && oi < i)) { v = ov; i = oi; }
            }
            if (lane == 0) out[2 * BATCH * SEQ + BATCH + row] = (float)i;
        }
    }
}

extern "C" void kernel_launch(void* const* d_in, const int* in_sizes, int n_in,
                              void* d_out, int out_size) {
    const float4* s4 = (const float4*)d_in[0];
    const float4* e4 = (const float4*)d_in[1];
    float* out = (float*)d_out;
    pred_head_zc<<<BATCH * 8, NTC>>>(s4, e4, out);
}